// round 1
// baseline (speedup 1.0000x reference)
#include <cuda_runtime.h>
#include <cuda_bf16.h>

#define Bz 4
#define Nn 2048
#define NF 512
#define ND 64
#define NH 4
#define NC 64
#define MAX_DEG 128
#define ALPHA 0.2f

// ---------------- scratch (static device globals; no runtime allocation) ----
__device__ float g_h[Bz * NH * Nn * ND];        // [b][h][n][d]   8 MB
__device__ float g_h1[Bz * Nn * NH * ND];       // [b][n][h*64+d] 8 MB (concat)
__device__ float g_g[Bz * Nn * NC];             // [b][n][c]      2 MB
__device__ float g_ssrc[Bz * NH * Nn];
__device__ float g_sdst[Bz * NH * Nn];
__device__ float g_tsrc[Bz * Nn];
__device__ float g_tdst[Bz * Nn];
__device__ int   g_cols[Nn * MAX_DEG];
__device__ int   g_deg[Nn];

// ---------------- 1. CSR build (warp per row, order-preserving ballot) ------
__global__ void build_csr_kernel(const float* __restrict__ adj) {
    int row  = (blockIdx.x * blockDim.x + threadIdx.x) >> 5;
    int lane = threadIdx.x & 31;
    if (row >= Nn) return;
    const float* ar = adj + (size_t)row * Nn;
    int base = 0;
    for (int c0 = 0; c0 < Nn; c0 += 32) {
        float v = ar[c0 + lane];
        unsigned m = __ballot_sync(0xffffffffu, v != 0.0f);
        if (v != 0.0f) {
            int pos = base + __popc(m & ((1u << lane) - 1u));
            if (pos < MAX_DEG) g_cols[row * MAX_DEG + pos] = c0 + lane;
        }
        base += __popc(m);
    }
    if (lane == 0) g_deg[row] = base < MAX_DEG ? base : MAX_DEG;
}

// ---------------- 2. h = x @ W1  ([8192,512] @ per-head [512,64]) -----------
// block: 256 threads, tile 64x64x16, 4x4 microtile. grid (128, NH).
__global__ void gemm_h_kernel(const float* __restrict__ X,
                              const float* __restrict__ W1) {
    __shared__ float As[16][68];
    __shared__ float Bs[16][64];
    int hh   = blockIdx.y;
    int row0 = blockIdx.x * 64;
    int tid  = threadIdx.x;
    int ty = tid >> 4, tx = tid & 15;
    float acc[4][4] = {};
    const float* Wb = W1 + (size_t)hh * NF * ND;
#pragma unroll 1
    for (int k0 = 0; k0 < NF; k0 += 16) {
        {   // A tile: 64 rows x 16 k
            int r = tid >> 2, kq = tid & 3;
            float4 v = *reinterpret_cast<const float4*>(
                X + (size_t)(row0 + r) * NF + k0 + kq * 4);
            As[kq * 4 + 0][r] = v.x; As[kq * 4 + 1][r] = v.y;
            As[kq * 4 + 2][r] = v.z; As[kq * 4 + 3][r] = v.w;
        }
        {   // B tile: 16 k x 64 d
            int k = tid >> 4, nq = tid & 15;
            float4 v = *reinterpret_cast<const float4*>(
                Wb + (size_t)(k0 + k) * ND + nq * 4);
            *reinterpret_cast<float4*>(&Bs[k][nq * 4]) = v;
        }
        __syncthreads();
#pragma unroll
        for (int kk = 0; kk < 16; kk++) {
            float a[4], bv[4];
#pragma unroll
            for (int i = 0; i < 4; i++) a[i] = As[kk][ty * 4 + i];
#pragma unroll
            for (int j = 0; j < 4; j++) bv[j] = Bs[kk][tx * 4 + j];
#pragma unroll
            for (int i = 0; i < 4; i++)
#pragma unroll
                for (int j = 0; j < 4; j++) acc[i][j] += a[i] * bv[j];
        }
        __syncthreads();
    }
#pragma unroll
    for (int i = 0; i < 4; i++) {
        int row = row0 + ty * 4 + i;
        int b = row >> 11, n = row & (Nn - 1);
        float* dst = g_h + (((size_t)(b * NH + hh) * Nn + n) * ND) + tx * 4;
        dst[0] = acc[i][0]; dst[1] = acc[i][1];
        dst[2] = acc[i][2]; dst[3] = acc[i][3];
    }
}

// ---------------- 3. s_src / s_dst (warp per (b,h,n)) -----------------------
__global__ void s_kernel(const float* __restrict__ a1) {
    int gw   = (blockIdx.x * blockDim.x + threadIdx.x) >> 5;
    int lane = threadIdx.x & 31;
    if (gw >= Bz * NH * Nn) return;
    int hh = (gw >> 11) & (NH - 1);
    const float* hr = g_h + (size_t)gw * ND;
    const float* av = a1 + hh * 2 * ND;
    float v0 = hr[lane], v1 = hr[lane + 32];
    float ss = v0 * av[lane]      + v1 * av[lane + 32];
    float sd = v0 * av[64 + lane] + v1 * av[96 + lane];
#pragma unroll
    for (int o = 16; o; o >>= 1) {
        ss += __shfl_down_sync(0xffffffffu, ss, o);
        sd += __shfl_down_sync(0xffffffffu, sd, o);
    }
    if (lane == 0) { g_ssrc[gw] = ss; g_sdst[gw] = sd; }
}

// ---------------- 4. sparse attention layer 1 (warp per (b,h,n)) ------------
__global__ void attn1_kernel() {
    int gw   = (blockIdx.x * blockDim.x + threadIdx.x) >> 5;
    int lane = threadIdx.x & 31;
    if (gw >= Bz * NH * Nn) return;
    int n  = gw & (Nn - 1);
    int bh = gw >> 11;
    int hh = bh & (NH - 1);
    int b  = bh >> 2;
    const float* hbase = g_h + (size_t)bh * Nn * ND;
    const float* sd    = g_sdst + (size_t)bh * Nn;
    float si = g_ssrc[gw];
    int dg = g_deg[n];
    const int* cr = g_cols + n * MAX_DEG;
    float acc0 = 0.f, acc1 = 0.f, den = 0.f;
    for (int k = 0; k < dg; k++) {
        int m = cr[k];
        float z  = si + sd[m];
        float lr = z > 0.f ? z : ALPHA * z;
        float e  = __expf(-lr);
        den += e;
        const float* hm = hbase + (size_t)m * ND;
        acc0 += e * hm[lane];
        acc1 += e * hm[lane + 32];
    }
    float inv = 1.0f / den;
    float o0 = acc0 * inv, o1 = acc1 * inv;
    o0 = o0 > 0.f ? o0 : expm1f(o0);   // elu (concat=True -> elu in layer)
    o1 = o1 > 0.f ? o1 : expm1f(o1);
    float* dst = g_h1 + ((size_t)(b * Nn + n)) * (NH * ND) + hh * ND;
    dst[lane] = o0; dst[lane + 32] = o1;
}

// ---------------- 5. g = h1 @ W2  ([8192,256] @ [256,64]) -------------------
__global__ void gemm_g_kernel(const float* __restrict__ W2) {
    __shared__ float As[16][68];
    __shared__ float Bs[16][64];
    int row0 = blockIdx.x * 64;
    int tid  = threadIdx.x;
    int ty = tid >> 4, tx = tid & 15;
    float acc[4][4] = {};
    const int K = NH * ND;  // 256
#pragma unroll 1
    for (int k0 = 0; k0 < K; k0 += 16) {
        {
            int r = tid >> 2, kq = tid & 3;
            float4 v = *reinterpret_cast<const float4*>(
                g_h1 + (size_t)(row0 + r) * K + k0 + kq * 4);
            As[kq * 4 + 0][r] = v.x; As[kq * 4 + 1][r] = v.y;
            As[kq * 4 + 2][r] = v.z; As[kq * 4 + 3][r] = v.w;
        }
        {
            int k = tid >> 4, nq = tid & 15;
            float4 v = *reinterpret_cast<const float4*>(
                W2 + (size_t)(k0 + k) * NC + nq * 4);
            *reinterpret_cast<float4*>(&Bs[k][nq * 4]) = v;
        }
        __syncthreads();
#pragma unroll
        for (int kk = 0; kk < 16; kk++) {
            float a[4], bv[4];
#pragma unroll
            for (int i = 0; i < 4; i++) a[i] = As[kk][ty * 4 + i];
#pragma unroll
            for (int j = 0; j < 4; j++) bv[j] = Bs[kk][tx * 4 + j];
#pragma unroll
            for (int i = 0; i < 4; i++)
#pragma unroll
                for (int j = 0; j < 4; j++) acc[i][j] += a[i] * bv[j];
        }
        __syncthreads();
    }
#pragma unroll
    for (int i = 0; i < 4; i++) {
        int row = row0 + ty * 4 + i;
        float* dst = g_g + (size_t)row * NC + tx * 4;
        dst[0] = acc[i][0]; dst[1] = acc[i][1];
        dst[2] = acc[i][2]; dst[3] = acc[i][3];
    }
}

// ---------------- 6. t_src / t_dst (warp per (b,n)) -------------------------
__global__ void t_kernel(const float* __restrict__ a2) {
    int gw   = (blockIdx.x * blockDim.x + threadIdx.x) >> 5;
    int lane = threadIdx.x & 31;
    if (gw >= Bz * Nn) return;
    const float* gr = g_g + (size_t)gw * NC;
    float v0 = gr[lane], v1 = gr[lane + 32];
    float ts = v0 * a2[lane]      + v1 * a2[lane + 32];
    float td = v0 * a2[64 + lane] + v1 * a2[96 + lane];
#pragma unroll
    for (int o = 16; o; o >>= 1) {
        ts += __shfl_down_sync(0xffffffffu, ts, o);
        td += __shfl_down_sync(0xffffffffu, td, o);
    }
    if (lane == 0) { g_tsrc[gw] = ts; g_tdst[gw] = td; }
}

// ---------------- 7. sparse attention layer 2 + final elu -------------------
__global__ void attn2_kernel(float* __restrict__ out) {
    int gw   = (blockIdx.x * blockDim.x + threadIdx.x) >> 5;
    int lane = threadIdx.x & 31;
    if (gw >= Bz * Nn) return;
    int n = gw & (Nn - 1);
    int b = gw >> 11;
    const float* gbase = g_g + (size_t)b * Nn * NC;
    const float* td    = g_tdst + (size_t)b * Nn;
    float ti = g_tsrc[gw];
    int dg = g_deg[n];
    const int* cr = g_cols + n * MAX_DEG;
    float acc0 = 0.f, acc1 = 0.f, den = 0.f;
    for (int k = 0; k < dg; k++) {
        int m = cr[k];
        float z  = ti + td[m];
        float lr = z > 0.f ? z : ALPHA * z;
        float e  = __expf(-lr);
        den += e;
        const float* gm = gbase + (size_t)m * NC;
        acc0 += e * gm[lane];
        acc1 += e * gm[lane + 32];
    }
    float inv = 1.0f / den;
    float o0 = acc0 * inv, o1 = acc1 * inv;
    o0 = o0 > 0.f ? o0 : expm1f(o0);   // outer F.elu
    o1 = o1 > 0.f ? o1 : expm1f(o1);
    float* dst = out + (size_t)gw * NC;
    dst[lane] = o0; dst[lane + 32] = o1;
}

// ---------------- launch -----------------------------------------------------
extern "C" void kernel_launch(void* const* d_in, const int* in_sizes, int n_in,
                              void* d_out, int out_size) {
    const float* x   = (const float*)d_in[0];
    const float* adj = (const float*)d_in[1];
    const float* W1  = (const float*)d_in[2];
    const float* a1  = (const float*)d_in[3];
    const float* W2  = (const float*)d_in[4];
    const float* a2  = (const float*)d_in[5];
    float* out = (float*)d_out;

    build_csr_kernel<<<(Nn * 32) / 256, 256>>>(adj);
    gemm_h_kernel<<<dim3(Bz * Nn / 64, NH), 256>>>(x, W1);
    s_kernel<<<(Bz * NH * Nn * 32) / 256, 256>>>(a1);
    attn1_kernel<<<(Bz * NH * Nn * 32) / 256, 256>>>();
    gemm_g_kernel<<<Bz * Nn / 64, 256>>>(W2);
    t_kernel<<<(Bz * Nn * 32) / 256, 256>>>(a2);
    attn2_kernel<<<(Bz * Nn * 32) / 256, 256>>>(out);
}

// round 2
// speedup vs baseline: 1.0057x; 1.0057x over previous
#include <cuda_runtime.h>
#include <cuda_bf16.h>

#define Bz 4
#define Nn 2048
#define NF 512
#define ND 64
#define NH 4
#define NC 64
#define MAX_DEG 128
#define ALPHA 0.2f

// ---------------- scratch ----------------------------------------------------
__device__ float g_h[Bz * NH * Nn * ND];        // [b][h][n][d]   8 MB
__device__ float g_h1[Bz * Nn * NH * ND];       // [b][n][h*64+d] 8 MB
__device__ float g_g[Bz * Nn * NC];             // [b][n][c]      2 MB
__device__ float g_ssrc[Bz * NH * Nn];
__device__ float g_sdst[Bz * NH * Nn];
__device__ float g_tsrc[Bz * Nn];
__device__ float g_tdst[Bz * Nn];
__device__ int   g_cols[Nn * MAX_DEG];
__device__ int   g_deg[Nn];

union U2 { unsigned long long u; float2 f; };

__device__ __forceinline__ unsigned long long pack_dup(float a) {
    unsigned long long r;
    asm("mov.b64 %0, {%1, %1};" : "=l"(r) : "f"(a));
    return r;
}
__device__ __forceinline__ void fma2(unsigned long long& d,
                                     unsigned long long a,
                                     unsigned long long b) {
    asm("fma.rn.f32x2 %0, %1, %2, %0;" : "+l"(d) : "l"(a), "l"(b));
}
__device__ __forceinline__ float edge_e(float si, float sdm) {
    float z  = si + sdm;
    float lr = z > 0.f ? z : ALPHA * z;
    return __expf(-lr);
}

// ---------------- 1. CSR build ----------------------------------------------
__global__ void build_csr_kernel(const float* __restrict__ adj) {
    int row  = (blockIdx.x * blockDim.x + threadIdx.x) >> 5;
    int lane = threadIdx.x & 31;
    if (row >= Nn) return;
    const float* ar = adj + (size_t)row * Nn;
    int base = 0;
    for (int c0 = 0; c0 < Nn; c0 += 32) {
        float v = ar[c0 + lane];
        unsigned m = __ballot_sync(0xffffffffu, v != 0.0f);
        if (v != 0.0f) {
            int pos = base + __popc(m & ((1u << lane) - 1u));
            if (pos < MAX_DEG) g_cols[row * MAX_DEG + pos] = c0 + lane;
        }
        base += __popc(m);
    }
    if (lane == 0) g_deg[row] = base < MAX_DEG ? base : MAX_DEG;
}

// ---------------- 2. gemm1: h = x@W1, fused s_src/s_dst ----------------------
// tile M=256 x N=64, K-step 16, 256 threads, 8x8 microtile via fma.rn.f32x2
__global__ void gemm1_kernel(const float* __restrict__ X,
                             const float* __restrict__ W1,
                             const float* __restrict__ a1) {
    __shared__ float As[16][256];
    __shared__ float Bs[16][64];
    int hh   = blockIdx.y;
    int row0 = blockIdx.x * 256;
    int tid  = threadIdx.x;
    int tx = tid & 7, ty = tid >> 3;
    unsigned long long acc[8][4];
#pragma unroll
    for (int i = 0; i < 8; i++)
#pragma unroll
        for (int j = 0; j < 4; j++) acc[i][j] = 0ull;

    const float* Wb = W1 + (size_t)hh * NF * ND;
#pragma unroll 1
    for (int k0 = 0; k0 < NF; k0 += 16) {
        {   // A: thread tid loads X[row0+tid][k0..k0+15], transpose into As
            const float* xr = X + (size_t)(row0 + tid) * NF + k0;
            float4 v0 = *reinterpret_cast<const float4*>(xr + 0);
            float4 v1 = *reinterpret_cast<const float4*>(xr + 4);
            float4 v2 = *reinterpret_cast<const float4*>(xr + 8);
            float4 v3 = *reinterpret_cast<const float4*>(xr + 12);
            As[0][tid] = v0.x;  As[1][tid] = v0.y;  As[2][tid] = v0.z;  As[3][tid] = v0.w;
            As[4][tid] = v1.x;  As[5][tid] = v1.y;  As[6][tid] = v1.z;  As[7][tid] = v1.w;
            As[8][tid] = v2.x;  As[9][tid] = v2.y;  As[10][tid] = v2.z; As[11][tid] = v2.w;
            As[12][tid] = v3.x; As[13][tid] = v3.y; As[14][tid] = v3.z; As[15][tid] = v3.w;
        }
        {   // B tile: 16 k x 64 n
            int bk = tid >> 4, bn = tid & 15;
            float4 v = *reinterpret_cast<const float4*>(Wb + (size_t)(k0 + bk) * ND + bn * 4);
            *reinterpret_cast<float4*>(&Bs[bk][bn * 4]) = v;
        }
        __syncthreads();
#pragma unroll
        for (int kk = 0; kk < 16; kk++) {
            float4 av0 = *reinterpret_cast<const float4*>(&As[kk][ty * 8]);
            float4 av1 = *reinterpret_cast<const float4*>(&As[kk][ty * 8 + 4]);
            unsigned long long bb[4];
#pragma unroll
            for (int j = 0; j < 4; j++)
                bb[j] = *reinterpret_cast<const unsigned long long*>(&Bs[kk][tx * 8 + 2 * j]);
            float a_arr[8] = {av0.x, av0.y, av0.z, av0.w, av1.x, av1.y, av1.z, av1.w};
#pragma unroll
            for (int i = 0; i < 8; i++) {
                unsigned long long aa = pack_dup(a_arr[i]);
#pragma unroll
                for (int j = 0; j < 4; j++) fma2(acc[i][j], aa, bb[j]);
            }
        }
        __syncthreads();
    }
    // epilogue: store h + fused s_src/s_dst
    const float* av = a1 + hh * 2 * ND;
    float asv[8], adv[8];
#pragma unroll
    for (int j = 0; j < 8; j++) {
        asv[j] = av[tx * 8 + j];
        adv[j] = av[64 + tx * 8 + j];
    }
#pragma unroll
    for (int i = 0; i < 8; i++) {
        U2 t0, t1, t2, t3;
        t0.u = acc[i][0]; t1.u = acc[i][1]; t2.u = acc[i][2]; t3.u = acc[i][3];
        float hv[8] = {t0.f.x, t0.f.y, t1.f.x, t1.f.y, t2.f.x, t2.f.y, t3.f.x, t3.f.y};
        float ss = 0.f, sdp = 0.f;
#pragma unroll
        for (int j = 0; j < 8; j++) { ss += hv[j] * asv[j]; sdp += hv[j] * adv[j]; }
#pragma unroll
        for (int o = 1; o < 8; o <<= 1) {
            ss  += __shfl_xor_sync(0xffffffffu, ss, o);
            sdp += __shfl_xor_sync(0xffffffffu, sdp, o);
        }
        int r = row0 + ty * 8 + i;
        int b = r >> 11, n = r & (Nn - 1);
        float* dst = g_h + ((size_t)(b * NH + hh) * Nn + n) * ND + tx * 8;
        *reinterpret_cast<float4*>(dst)     = make_float4(hv[0], hv[1], hv[2], hv[3]);
        *reinterpret_cast<float4*>(dst + 4) = make_float4(hv[4], hv[5], hv[6], hv[7]);
        if (tx == 0) {
            int gw = (b * NH + hh) * Nn + n;
            g_ssrc[gw] = ss;
            g_sdst[gw] = sdp;
        }
    }
}

// ---------------- 3. sparse attention layer 1 (warp per (b,h,n)) ------------
__global__ void attn1_kernel() {
    int gw   = (blockIdx.x * blockDim.x + threadIdx.x) >> 5;
    int lane = threadIdx.x & 31;
    if (gw >= Bz * NH * Nn) return;
    int n  = gw & (Nn - 1);
    int bh = gw >> 11;
    int hh = bh & (NH - 1);
    int b  = bh >> 2;
    const float2* hb = reinterpret_cast<const float2*>(g_h + (size_t)bh * Nn * ND);
    const float*  sd = g_sdst + (size_t)bh * Nn;
    float si = g_ssrc[gw];
    int dg = g_deg[n];
    const int* cr = g_cols + n * MAX_DEG;
    float2 acc = {0.f, 0.f};
    float den = 0.f;
    int k = 0;
    for (; k + 4 <= dg; k += 4) {
        int4 mm = *reinterpret_cast<const int4*>(cr + k);
        float e0 = edge_e(si, sd[mm.x]);
        float e1 = edge_e(si, sd[mm.y]);
        float e2 = edge_e(si, sd[mm.z]);
        float e3 = edge_e(si, sd[mm.w]);
        float2 v0 = hb[(size_t)mm.x * 32 + lane];
        float2 v1 = hb[(size_t)mm.y * 32 + lane];
        float2 v2 = hb[(size_t)mm.z * 32 + lane];
        float2 v3 = hb[(size_t)mm.w * 32 + lane];
        den += (e0 + e1) + (e2 + e3);
        acc.x += e0 * v0.x; acc.y += e0 * v0.y;
        acc.x += e1 * v1.x; acc.y += e1 * v1.y;
        acc.x += e2 * v2.x; acc.y += e2 * v2.y;
        acc.x += e3 * v3.x; acc.y += e3 * v3.y;
    }
    for (; k < dg; k++) {
        int m = cr[k];
        float e = edge_e(si, sd[m]);
        float2 v = hb[(size_t)m * 32 + lane];
        den += e;
        acc.x += e * v.x; acc.y += e * v.y;
    }
    float inv = 1.0f / den;
    float o0 = acc.x * inv, o1 = acc.y * inv;
    o0 = o0 > 0.f ? o0 : expm1f(o0);
    o1 = o1 > 0.f ? o1 : expm1f(o1);
    float* dst = g_h1 + ((size_t)(b * Nn + n)) * (NH * ND) + hh * ND + lane * 2;
    dst[0] = o0; dst[1] = o1;
}

// ---------------- 4. gemm2: g = h1@W2, fused t_src/t_dst ---------------------
// tile 64x64, K=256, 4x4 microtile, 256 threads
__global__ void gemm2_kernel(const float* __restrict__ W2,
                             const float* __restrict__ a2) {
    __shared__ float As[16][68];
    __shared__ float Bs[16][64];
    int row0 = blockIdx.x * 64;
    int tid  = threadIdx.x;
    int ty = tid >> 4, tx = tid & 15;
    float acc[4][4] = {};
    const int K = NH * ND;  // 256
#pragma unroll 1
    for (int k0 = 0; k0 < K; k0 += 16) {
        {
            int r = tid >> 2, kq = tid & 3;
            float4 v = *reinterpret_cast<const float4*>(
                g_h1 + (size_t)(row0 + r) * K + k0 + kq * 4);
            As[kq * 4 + 0][r] = v.x; As[kq * 4 + 1][r] = v.y;
            As[kq * 4 + 2][r] = v.z; As[kq * 4 + 3][r] = v.w;
        }
        {
            int kq = tid >> 4, nq = tid & 15;
            float4 v = *reinterpret_cast<const float4*>(
                W2 + (size_t)(k0 + kq) * NC + nq * 4);
            *reinterpret_cast<float4*>(&Bs[kq][nq * 4]) = v;
        }
        __syncthreads();
#pragma unroll
        for (int kk = 0; kk < 16; kk++) {
            float a[4], bv[4];
#pragma unroll
            for (int i = 0; i < 4; i++) a[i] = As[kk][ty * 4 + i];
#pragma unroll
            for (int j = 0; j < 4; j++) bv[j] = Bs[kk][tx * 4 + j];
#pragma unroll
            for (int i = 0; i < 4; i++)
#pragma unroll
                for (int j = 0; j < 4; j++) acc[i][j] += a[i] * bv[j];
        }
        __syncthreads();
    }
    float asv[4], adv[4];
#pragma unroll
    for (int j = 0; j < 4; j++) {
        asv[j] = a2[tx * 4 + j];
        adv[j] = a2[64 + tx * 4 + j];
    }
#pragma unroll
    for (int i = 0; i < 4; i++) {
        int r = row0 + ty * 4 + i;
        float ts = 0.f, td = 0.f;
#pragma unroll
        for (int j = 0; j < 4; j++) { ts += acc[i][j] * asv[j]; td += acc[i][j] * adv[j]; }
#pragma unroll
        for (int o = 1; o < 16; o <<= 1) {
            ts += __shfl_xor_sync(0xffffffffu, ts, o);
            td += __shfl_xor_sync(0xffffffffu, td, o);
        }
        float* dst = g_g + (size_t)r * NC + tx * 4;
        dst[0] = acc[i][0]; dst[1] = acc[i][1];
        dst[2] = acc[i][2]; dst[3] = acc[i][3];
        if (tx == 0) { g_tsrc[r] = ts; g_tdst[r] = td; }
    }
}

// ---------------- 5. sparse attention layer 2 + final elu --------------------
__global__ void attn2_kernel(float* __restrict__ out) {
    int gw   = (blockIdx.x * blockDim.x + threadIdx.x) >> 5;
    int lane = threadIdx.x & 31;
    if (gw >= Bz * Nn) return;
    int n = gw & (Nn - 1);
    int b = gw >> 11;
    const float2* gb = reinterpret_cast<const float2*>(g_g + (size_t)b * Nn * NC);
    const float*  td = g_tdst + (size_t)b * Nn;
    float ti = g_tsrc[gw];
    int dg = g_deg[n];
    const int* cr = g_cols + n * MAX_DEG;
    float2 acc = {0.f, 0.f};
    float den = 0.f;
    int k = 0;
    for (; k + 4 <= dg; k += 4) {
        int4 mm = *reinterpret_cast<const int4*>(cr + k);
        float e0 = edge_e(ti, td[mm.x]);
        float e1 = edge_e(ti, td[mm.y]);
        float e2 = edge_e(ti, td[mm.z]);
        float e3 = edge_e(ti, td[mm.w]);
        float2 v0 = gb[(size_t)mm.x * 32 + lane];
        float2 v1 = gb[(size_t)mm.y * 32 + lane];
        float2 v2 = gb[(size_t)mm.z * 32 + lane];
        float2 v3 = gb[(size_t)mm.w * 32 + lane];
        den += (e0 + e1) + (e2 + e3);
        acc.x += e0 * v0.x; acc.y += e0 * v0.y;
        acc.x += e1 * v1.x; acc.y += e1 * v1.y;
        acc.x += e2 * v2.x; acc.y += e2 * v2.y;
        acc.x += e3 * v3.x; acc.y += e3 * v3.y;
    }
    for (; k < dg; k++) {
        int m = cr[k];
        float e = edge_e(ti, td[m]);
        float2 v = gb[(size_t)m * 32 + lane];
        den += e;
        acc.x += e * v.x; acc.y += e * v.y;
    }
    float inv = 1.0f / den;
    float o0 = acc.x * inv, o1 = acc.y * inv;
    o0 = o0 > 0.f ? o0 : expm1f(o0);
    o1 = o1 > 0.f ? o1 : expm1f(o1);
    float* dst = out + (size_t)gw * NC + lane * 2;
    dst[0] = o0; dst[1] = o1;
}

// ---------------- launch ------------------------------------------------------
extern "C" void kernel_launch(void* const* d_in, const int* in_sizes, int n_in,
                              void* d_out, int out_size) {
    const float* x   = (const float*)d_in[0];
    const float* adj = (const float*)d_in[1];
    const float* W1  = (const float*)d_in[2];
    const float* a1  = (const float*)d_in[3];
    const float* W2  = (const float*)d_in[4];
    const float* a2  = (const float*)d_in[5];
    float* out = (float*)d_out;

    build_csr_kernel<<<(Nn * 32) / 256, 256>>>(adj);
    gemm1_kernel<<<dim3(Bz * Nn / 256, NH), 256>>>(x, W1, a1);
    attn1_kernel<<<(Bz * NH * Nn * 32) / 256, 256>>>();
    gemm2_kernel<<<Bz * Nn / 64, 256>>>(W2, a2);
    attn2_kernel<<<(Bz * Nn * 32) / 256, 256>>>(out);
}

// round 4
// speedup vs baseline: 1.4673x; 1.4591x over previous
#include <cuda_runtime.h>
#include <cstdint>

#define Bz 4
#define Nn 2048
#define NF 512
#define ND 64
#define NH 4
#define NC 64
#define MAX_DEG 128
#define ALPHA 0.2f

// ---------------- scratch -----------------------------------------------------
__device__ __align__(16) float g_h [Bz * Nn * NH * ND];   // [b][n][h*64+d] 8MB
__device__ __align__(16) float g_h1[Bz * Nn * NH * ND];   // [b][n][h*64+d] 8MB
__device__ __align__(16) float g_g [Bz * Nn * NC];        // [b][n][c]      2MB
__device__ __align__(16) float g_W1t[NH * ND * NF];       // [256][512]
__device__ __align__(16) float g_W2t[NC * NH * ND];       // [64][256]
__device__ float g_ssrc[Bz * NH * Nn];
__device__ float g_sdst[Bz * NH * Nn];
__device__ float g_tsrc[Bz * Nn];
__device__ float g_tdst[Bz * Nn];
__device__ int   g_cols[Nn * MAX_DEG];
__device__ int   g_deg[Nn];

// ---------------- helpers ------------------------------------------------------
__device__ __forceinline__ float totf(float x) {
    uint32_t u;
    asm("cvt.rna.tf32.f32 %0, %1;" : "=r"(u) : "f"(x));
    return __uint_as_float(u);
}
__device__ __forceinline__ void mma8(float* c,
                                     uint32_t a0, uint32_t a1, uint32_t a2, uint32_t a3,
                                     uint32_t b0, uint32_t b1) {
    asm volatile(
        "mma.sync.aligned.m16n8k8.row.col.f32.tf32.tf32.f32 "
        "{%0,%1,%2,%3}, {%4,%5,%6,%7}, {%8,%9}, {%0,%1,%2,%3};"
        : "+f"(c[0]), "+f"(c[1]), "+f"(c[2]), "+f"(c[3])
        : "r"(a0), "r"(a1), "r"(a2), "r"(a3), "r"(b0), "r"(b1));
}
__device__ __forceinline__ float edge_e(float si, float sdm) {
    float z = si + sdm;
    float lr = z > 0.f ? z : ALPHA * z;
    return __expf(-lr);
}

// ---------------- transposes ----------------------------------------------------
__global__ void transposeW1_kernel(const float* __restrict__ W1) {
    __shared__ float t[32][33];
    int h = blockIdx.z, k0 = blockIdx.x * 32, d0 = blockIdx.y * 32;
    int tx = threadIdx.x, ty = threadIdx.y;
    const float* Wb = W1 + (size_t)h * NF * ND;
#pragma unroll
    for (int i = 0; i < 4; i++) t[ty + i * 8][tx] = Wb[(size_t)(k0 + ty + i * 8) * ND + d0 + tx];
    __syncthreads();
#pragma unroll
    for (int i = 0; i < 4; i++)
        g_W1t[(size_t)(h * 64 + d0 + ty + i * 8) * NF + k0 + tx] = t[tx][ty + i * 8];
}
__global__ void transposeW2_kernel(const float* __restrict__ W2) {
    __shared__ float t[32][33];
    int k0 = blockIdx.x * 32, c0 = blockIdx.y * 32;
    int tx = threadIdx.x, ty = threadIdx.y;
#pragma unroll
    for (int i = 0; i < 4; i++) t[ty + i * 8][tx] = W2[(size_t)(k0 + ty + i * 8) * NC + c0 + tx];
    __syncthreads();
#pragma unroll
    for (int i = 0; i < 4; i++)
        g_W2t[(size_t)(c0 + ty + i * 8) * (NH * ND) + k0 + tx] = t[tx][ty + i * 8];
}

// ---------------- CSR build ------------------------------------------------------
__global__ void build_csr_kernel(const float* __restrict__ adj) {
    int row  = (blockIdx.x * blockDim.x + threadIdx.x) >> 5;
    int lane = threadIdx.x & 31;
    if (row >= Nn) return;
    const float* ar = adj + (size_t)row * Nn;
    int base = 0;
    for (int c0 = 0; c0 < Nn; c0 += 32) {
        float v = ar[c0 + lane];
        unsigned m = __ballot_sync(0xffffffffu, v != 0.0f);
        if (v != 0.0f) {
            int pos = base + __popc(m & ((1u << lane) - 1u));
            if (pos < MAX_DEG) g_cols[row * MAX_DEG + pos] = c0 + lane;
        }
        base += __popc(m);
    }
    if (lane == 0) g_deg[row] = base < MAX_DEG ? base : MAX_DEG;
}

// ---------------- gemm1: h = X @ W1t^T via tf32 mma.sync, fused s dots ----------
// CTA 128x128, K-step 32, grid (64, 2). 8 warps = 4(M) x 2(N), warp tile 32x64.
#define PAD 36
__global__ void __launch_bounds__(256, 1) gemm1_mma(const float* __restrict__ X,
                                                    const float* __restrict__ a1) {
    extern __shared__ float sm[];
    float* sA  = sm;                 // [2][128][36]
    float* sB  = sm + 2 * 128 * PAD; // [2][128][36]
    float* sa1 = sB + 2 * 128 * PAD; // [512]
    const int tid = threadIdx.x, lane = tid & 31, warp = tid >> 5;
    const int wm = warp & 3, wn = warp >> 2;
    const int g = lane >> 2, tig = lane & 3;
    const int row0 = blockIdx.x * 128, col0 = blockIdx.y * 128;
    sa1[tid] = a1[tid]; sa1[tid + 256] = a1[tid + 256];

    const int lr = tid >> 1, lk = (tid & 1) * 16;
    const float* asrc = X + (size_t)(row0 + lr) * NF + lk;
    const float* bsrc = g_W1t + (size_t)(col0 + lr) * NF + lk;

    float c[2][8][4];
#pragma unroll
    for (int i = 0; i < 2; i++)
#pragma unroll
        for (int j = 0; j < 8; j++)
#pragma unroll
            for (int q = 0; q < 4; q++) c[i][j][q] = 0.f;

    float4 ra[4], rb[4];
#define LDG_T(kb)                                                   \
    do {                                                            \
        _Pragma("unroll")                                           \
        for (int i = 0; i < 4; i++) {                               \
            ra[i] = *(const float4*)(asrc + (kb) + 4 * i);          \
            rb[i] = *(const float4*)(bsrc + (kb) + 4 * i);          \
        }                                                           \
    } while (0)
#define STS_T(bf)                                                   \
    do {                                                            \
        _Pragma("unroll")                                           \
        for (int i = 0; i < 4; i++) {                               \
            float4 v = ra[i];                                       \
            v.x = totf(v.x); v.y = totf(v.y);                       \
            v.z = totf(v.z); v.w = totf(v.w);                       \
            *(float4*)&sA[(bf) * 128 * PAD + lr * PAD + lk + 4 * i] = v; \
            v = rb[i];                                              \
            v.x = totf(v.x); v.y = totf(v.y);                       \
            v.z = totf(v.z); v.w = totf(v.w);                       \
            *(float4*)&sB[(bf) * 128 * PAD + lr * PAD + lk + 4 * i] = v; \
        }                                                           \
    } while (0)

    LDG_T(0);
    STS_T(0);
    __syncthreads();

#pragma unroll 1
    for (int kt = 0; kt < 16; ++kt) {
        const int buf = kt & 1;
        if (kt < 15) LDG_T((kt + 1) * 32);
        const float* A0 = sA + buf * 128 * PAD;
        const float* B0 = sB + buf * 128 * PAD;
#pragma unroll
        for (int s8 = 0; s8 < 4; ++s8) {
            const int kf = s8 * 8 + tig;
            uint32_t af[2][4];
#pragma unroll
            for (int ma = 0; ma < 2; ma++) {
                const float* ar0 = A0 + (wm * 32 + ma * 16 + g) * PAD;
                af[ma][0] = __float_as_uint(ar0[kf]);
                af[ma][1] = __float_as_uint(ar0[8 * PAD + kf]);
                af[ma][2] = __float_as_uint(ar0[kf + 4]);
                af[ma][3] = __float_as_uint(ar0[8 * PAD + kf + 4]);
            }
#pragma unroll
            for (int j = 0; j < 8; j++) {
                const float* br0 = B0 + (wn * 64 + 8 * j + g) * PAD;
                uint32_t b0 = __float_as_uint(br0[kf]);
                uint32_t b1 = __float_as_uint(br0[kf + 4]);
                mma8(c[0][j], af[0][0], af[0][1], af[0][2], af[0][3], b0, b1);
                mma8(c[1][j], af[1][0], af[1][1], af[1][2], af[1][3], b0, b1);
            }
        }
        if (kt < 15) {
            STS_T((kt + 1) & 1);
            __syncthreads();
        }
    }

    // epilogue: store h rows + fused s_src/s_dst (warp's 64 cols == one head)
    const int head = blockIdx.y * 2 + wn;
    const float* ahs = sa1 + head * 128;
#pragma unroll
    for (int ma = 0; ma < 2; ma++) {
        float slo = 0.f, dlo = 0.f, shi = 0.f, dhi = 0.f;
#pragma unroll
        for (int j = 0; j < 8; j++) {
            const int col = 8 * j + 2 * tig;
            float w0 = ahs[col], w1 = ahs[col + 1];
            float u0 = ahs[64 + col], u1 = ahs[64 + col + 1];
            slo += c[ma][j][0] * w0 + c[ma][j][1] * w1;
            dlo += c[ma][j][0] * u0 + c[ma][j][1] * u1;
            shi += c[ma][j][2] * w0 + c[ma][j][3] * w1;
            dhi += c[ma][j][2] * u0 + c[ma][j][3] * u1;
        }
#pragma unroll
        for (int o = 1; o < 4; o <<= 1) {
            slo += __shfl_xor_sync(0xffffffffu, slo, o);
            dlo += __shfl_xor_sync(0xffffffffu, dlo, o);
            shi += __shfl_xor_sync(0xffffffffu, shi, o);
            dhi += __shfl_xor_sync(0xffffffffu, dhi, o);
        }
        const int rlo = row0 + wm * 32 + ma * 16 + g;
        const int rhi = rlo + 8;
        float* dst0 = g_h + (size_t)rlo * 256 + head * 64;
        float* dst1 = g_h + (size_t)rhi * 256 + head * 64;
#pragma unroll
        for (int j = 0; j < 8; j++) {
            const int col = 8 * j + 2 * tig;
            *(float2*)(dst0 + col) = make_float2(c[ma][j][0], c[ma][j][1]);
            *(float2*)(dst1 + col) = make_float2(c[ma][j][2], c[ma][j][3]);
        }
        if (tig == 0) {
            int b0i = rlo >> 11, n0i = rlo & (Nn - 1);
            int b1i = rhi >> 11, n1i = rhi & (Nn - 1);
            g_ssrc[(b0i * NH + head) * Nn + n0i] = slo;
            g_sdst[(b0i * NH + head) * Nn + n0i] = dlo;
            g_ssrc[(b1i * NH + head) * Nn + n1i] = shi;
            g_sdst[(b1i * NH + head) * Nn + n1i] = dhi;
        }
    }
#undef LDG_T
#undef STS_T
}

// ---------------- gemm2: g = h1 @ W2t^T via tf32 mma.sync, fused t dots ---------
// CTA 128x64, K=256 (8 steps of 32), grid 64. 8 warps, warp tile 16x64.
__global__ void __launch_bounds__(256, 1) gemm2_mma(const float* __restrict__ a2) {
    extern __shared__ float sm[];
    float* sA  = sm;                 // [2][128][36]
    float* sB  = sm + 2 * 128 * PAD; // [2][64][36]
    float* sa2 = sB + 2 * 64 * PAD;  // [128]
    const int tid = threadIdx.x, lane = tid & 31, warp = tid >> 5;
    const int g = lane >> 2, tig = lane & 3;
    const int row0 = blockIdx.x * 128;
    const int K = NH * ND;  // 256
    if (tid < 128) sa2[tid] = a2[tid];

    const int lr = tid >> 1, lk = (tid & 1) * 16;
    const float* asrc = g_h1 + (size_t)(row0 + lr) * K + lk;
    const bool bld = (tid < 128);
    const float* bsrc = g_W2t + (size_t)(bld ? lr : 0) * K + lk;

    float c[8][4];
#pragma unroll
    for (int j = 0; j < 8; j++)
#pragma unroll
        for (int q = 0; q < 4; q++) c[j][q] = 0.f;

    float4 ra[4], rb[4];
#define LDG_T2(kb)                                                  \
    do {                                                            \
        _Pragma("unroll")                                           \
        for (int i = 0; i < 4; i++) {                               \
            ra[i] = *(const float4*)(asrc + (kb) + 4 * i);          \
            if (bld) rb[i] = *(const float4*)(bsrc + (kb) + 4 * i); \
        }                                                           \
    } while (0)
#define STS_T2(bf)                                                  \
    do {                                                            \
        _Pragma("unroll")                                           \
        for (int i = 0; i < 4; i++) {                               \
            float4 v = ra[i];                                       \
            v.x = totf(v.x); v.y = totf(v.y);                       \
            v.z = totf(v.z); v.w = totf(v.w);                       \
            *(float4*)&sA[(bf) * 128 * PAD + lr * PAD + lk + 4 * i] = v; \
            if (bld) {                                              \
                v = rb[i];                                          \
                v.x = totf(v.x); v.y = totf(v.y);                   \
                v.z = totf(v.z); v.w = totf(v.w);                   \
                *(float4*)&sB[(bf) * 64 * PAD + lr * PAD + lk + 4 * i] = v; \
            }                                                       \
        }                                                           \
    } while (0)

    LDG_T2(0);
    STS_T2(0);
    __syncthreads();

#pragma unroll 1
    for (int kt = 0; kt < 8; ++kt) {
        const int buf = kt & 1;
        if (kt < 7) LDG_T2((kt + 1) * 32);
        const float* A0 = sA + buf * 128 * PAD;
        const float* B0 = sB + buf * 64 * PAD;
#pragma unroll
        for (int s8 = 0; s8 < 4; ++s8) {
            const int kf = s8 * 8 + tig;
            const float* ar0 = A0 + (warp * 16 + g) * PAD;
            uint32_t a0 = __float_as_uint(ar0[kf]);
            uint32_t a1r = __float_as_uint(ar0[8 * PAD + kf]);
            uint32_t a2r = __float_as_uint(ar0[kf + 4]);
            uint32_t a3 = __float_as_uint(ar0[8 * PAD + kf + 4]);
#pragma unroll
            for (int j = 0; j < 8; j++) {
                const float* br0 = B0 + (8 * j + g) * PAD;
                uint32_t b0 = __float_as_uint(br0[kf]);
                uint32_t b1 = __float_as_uint(br0[kf + 4]);
                mma8(c[j], a0, a1r, a2r, a3, b0, b1);
            }
        }
        if (kt < 7) {
            STS_T2((kt + 1) & 1);
            __syncthreads();
        }
    }

    // epilogue: store g + fused t_src/t_dst
    float slo = 0.f, dlo = 0.f, shi = 0.f, dhi = 0.f;
#pragma unroll
    for (int j = 0; j < 8; j++) {
        const int col = 8 * j + 2 * tig;
        float w0 = sa2[col], w1 = sa2[col + 1];
        float u0 = sa2[64 + col], u1 = sa2[64 + col + 1];
        slo += c[j][0] * w0 + c[j][1] * w1;
        dlo += c[j][0] * u0 + c[j][1] * u1;
        shi += c[j][2] * w0 + c[j][3] * w1;
        dhi += c[j][2] * u0 + c[j][3] * u1;
    }
#pragma unroll
    for (int o = 1; o < 4; o <<= 1) {
        slo += __shfl_xor_sync(0xffffffffu, slo, o);
        dlo += __shfl_xor_sync(0xffffffffu, dlo, o);
        shi += __shfl_xor_sync(0xffffffffu, shi, o);
        dhi += __shfl_xor_sync(0xffffffffu, dhi, o);
    }
    const int rlo = row0 + warp * 16 + g;
    const int rhi = rlo + 8;
    float* dst0 = g_g + (size_t)rlo * NC;
    float* dst1 = g_g + (size_t)rhi * NC;
#pragma unroll
    for (int j = 0; j < 8; j++) {
        const int col = 8 * j + 2 * tig;
        *(float2*)(dst0 + col) = make_float2(c[j][0], c[j][1]);
        *(float2*)(dst1 + col) = make_float2(c[j][2], c[j][3]);
    }
    if (tig == 0) {
        g_tsrc[rlo] = slo; g_tdst[rlo] = dlo;
        g_tsrc[rhi] = shi; g_tdst[rhi] = dhi;
    }
#undef LDG_T2
#undef STS_T2
}

// ---------------- sparse attention layer 1 (warp per (b,h,n)) --------------------
__global__ void attn1_kernel() {
    int gw   = (blockIdx.x * blockDim.x + threadIdx.x) >> 5;
    int lane = threadIdx.x & 31;
    if (gw >= Bz * NH * Nn) return;
    int n  = gw & (Nn - 1);
    int bh = gw >> 11;
    int hh = bh & (NH - 1);
    int b  = bh >> 2;
    const float2* hb = reinterpret_cast<const float2*>(g_h) + (size_t)b * Nn * 128 + hh * 32;
    const float*  sd = g_sdst + (size_t)bh * Nn;
    float si = g_ssrc[gw];
    int dg = g_deg[n];
    const int* cr = g_cols + n * MAX_DEG;
    float2 acc = {0.f, 0.f};
    float den = 0.f;
    int k = 0;
    for (; k + 4 <= dg; k += 4) {
        int4 mm = *reinterpret_cast<const int4*>(cr + k);
        float e0 = edge_e(si, sd[mm.x]);
        float e1 = edge_e(si, sd[mm.y]);
        float e2 = edge_e(si, sd[mm.z]);
        float e3 = edge_e(si, sd[mm.w]);
        float2 v0 = hb[(size_t)mm.x * 128 + lane];
        float2 v1 = hb[(size_t)mm.y * 128 + lane];
        float2 v2 = hb[(size_t)mm.z * 128 + lane];
        float2 v3 = hb[(size_t)mm.w * 128 + lane];
        den += (e0 + e1) + (e2 + e3);
        acc.x += e0 * v0.x; acc.y += e0 * v0.y;
        acc.x += e1 * v1.x; acc.y += e1 * v1.y;
        acc.x += e2 * v2.x; acc.y += e2 * v2.y;
        acc.x += e3 * v3.x; acc.y += e3 * v3.y;
    }
    for (; k < dg; k++) {
        int m = cr[k];
        float e = edge_e(si, sd[m]);
        float2 v = hb[(size_t)m * 128 + lane];
        den += e;
        acc.x += e * v.x; acc.y += e * v.y;
    }
    float inv = 1.0f / den;
    float o0 = acc.x * inv, o1 = acc.y * inv;
    o0 = o0 > 0.f ? o0 : expm1f(o0);
    o1 = o1 > 0.f ? o1 : expm1f(o1);
    float* dst = g_h1 + ((size_t)(b * Nn + n)) * (NH * ND) + hh * ND + lane * 2;
    dst[0] = o0; dst[1] = o1;
}

// ---------------- sparse attention layer 2 + final elu ---------------------------
__global__ void attn2_kernel(float* __restrict__ out) {
    int gw   = (blockIdx.x * blockDim.x + threadIdx.x) >> 5;
    int lane = threadIdx.x & 31;
    if (gw >= Bz * Nn) return;
    int n = gw & (Nn - 1);
    int b = gw >> 11;
    const float2* gb = reinterpret_cast<const float2*>(g_g) + (size_t)b * Nn * 32;
    const float*  td = g_tdst + (size_t)b * Nn;
    float ti = g_tsrc[gw];
    int dg = g_deg[n];
    const int* cr = g_cols + n * MAX_DEG;
    float2 acc = {0.f, 0.f};
    float den = 0.f;
    int k = 0;
    for (; k + 4 <= dg; k += 4) {
        int4 mm = *reinterpret_cast<const int4*>(cr + k);
        float e0 = edge_e(ti, td[mm.x]);
        float e1 = edge_e(ti, td[mm.y]);
        float e2 = edge_e(ti, td[mm.z]);
        float e3 = edge_e(ti, td[mm.w]);
        float2 v0 = gb[(size_t)mm.x * 32 + lane];
        float2 v1 = gb[(size_t)mm.y * 32 + lane];
        float2 v2 = gb[(size_t)mm.z * 32 + lane];
        float2 v3 = gb[(size_t)mm.w * 32 + lane];
        den += (e0 + e1) + (e2 + e3);
        acc.x += e0 * v0.x; acc.y += e0 * v0.y;
        acc.x += e1 * v1.x; acc.y += e1 * v1.y;
        acc.x += e2 * v2.x; acc.y += e2 * v2.y;
        acc.x += e3 * v3.x; acc.y += e3 * v3.y;
    }
    for (; k < dg; k++) {
        int m = cr[k];
        float e = edge_e(ti, td[m]);
        float2 v = gb[(size_t)m * 32 + lane];
        den += e;
        acc.x += e * v.x; acc.y += e * v.y;
    }
    float inv = 1.0f / den;
    float o0 = acc.x * inv, o1 = acc.y * inv;
    o0 = o0 > 0.f ? o0 : expm1f(o0);
    o1 = o1 > 0.f ? o1 : expm1f(o1);
    float* dst = out + (size_t)gw * NC + lane * 2;
    dst[0] = o0; dst[1] = o1;
}

// ---------------- launch -----------------------------------------------------------
extern "C" void kernel_launch(void* const* d_in, const int* in_sizes, int n_in,
                              void* d_out, int out_size) {
    const float* x   = (const float*)d_in[0];
    const float* adj = (const float*)d_in[1];
    const float* W1  = (const float*)d_in[2];
    const float* a1  = (const float*)d_in[3];
    const float* W2  = (const float*)d_in[4];
    const float* a2  = (const float*)d_in[5];
    float* out = (float*)d_out;

    const int smem1 = (2 * 128 * PAD + 2 * 128 * PAD + 512) * 4;   // 75776 B
    const int smem2 = (2 * 128 * PAD + 2 * 64 * PAD + 128) * 4;    // 55808 B
    cudaFuncSetAttribute(gemm1_mma, cudaFuncAttributeMaxDynamicSharedMemorySize, smem1);
    cudaFuncSetAttribute(gemm2_mma, cudaFuncAttributeMaxDynamicSharedMemorySize, smem2);

    transposeW1_kernel<<<dim3(16, 2, 4), dim3(32, 8)>>>(W1);
    transposeW2_kernel<<<dim3(8, 2), dim3(32, 8)>>>(W2);
    build_csr_kernel<<<(Nn * 32) / 256, 256>>>(adj);
    gemm1_mma<<<dim3(64, 2), 256, smem1>>>(x, a1);
    attn1_kernel<<<(Bz * NH * Nn * 32) / 256, 256>>>();
    gemm2_mma<<<64, 256, smem2>>>(a2);
    attn2_kernel<<<(Bz * Nn * 32) / 256, 256>>>(out);
}